// round 1
// baseline (speedup 1.0000x reference)
#include <cuda_runtime.h>

#define TOKENS 8192
#define DIM    512
#define FDIM   128
#define NLEAF  8
#define BM     32
#define BK     16
#define TILES_PER_LEAF (TOKENS / BM)   // 256

// Scratch (static device globals — no allocation in kernel_launch)
__device__ int g_count[NLEAF];
__device__ int g_list[NLEAF * TOKENS];

__global__ void zero_kernel() {
    if (threadIdx.x < NLEAF) g_count[threadIdx.x] = 0;
}

__device__ __forceinline__ float warp_sum(float v) {
    #pragma unroll
    for (int o = 16; o > 0; o >>= 1) v += __shfl_xor_sync(0xFFFFFFFFu, v, o);
    return v;
}

// One warp per token: 3 path-dependent routing dots, then bucket the token.
__global__ void route_kernel(const float* __restrict__ x,
                             const float* __restrict__ wn0, const float* __restrict__ bn0,
                             const float* __restrict__ wn1, const float* __restrict__ bn1,
                             const float* __restrict__ wn2, const float* __restrict__ bn2)
{
    int gwarp = (blockIdx.x * blockDim.x + threadIdx.x) >> 5;
    int lane  = threadIdx.x & 31;
    if (gwarp >= TOKENS) return;

    const float4* xr4 = (const float4*)(x + (size_t)gwarp * DIM);
    float4 xv[4];
    #pragma unroll
    for (int i = 0; i < 4; i++) xv[i] = xr4[lane + i * 32];   // coalesced

    // depth 0 (n=1)
    float s = 0.f;
    #pragma unroll
    for (int i = 0; i < 4; i++) {
        int base = (lane + i * 32) * 4;
        s += xv[i].x * wn0[base + 0] + xv[i].y * wn0[base + 1]
           + xv[i].z * wn0[base + 2] + xv[i].w * wn0[base + 3];
    }
    s = warp_sum(s) + bn0[0];
    int node = (s > 0.f) ? 0 : 1;

    // depth 1 (n=2), column = node
    s = 0.f;
    #pragma unroll
    for (int i = 0; i < 4; i++) {
        int base = (lane + i * 32) * 4;
        s += xv[i].x * wn1[(base + 0) * 2 + node] + xv[i].y * wn1[(base + 1) * 2 + node]
           + xv[i].z * wn1[(base + 2) * 2 + node] + xv[i].w * wn1[(base + 3) * 2 + node];
    }
    s = warp_sum(s) + bn1[node];
    node = node * 2 + ((s > 0.f) ? 0 : 1);

    // depth 2 (n=4), column = node
    s = 0.f;
    #pragma unroll
    for (int i = 0; i < 4; i++) {
        int base = (lane + i * 32) * 4;
        s += xv[i].x * wn2[(base + 0) * 4 + node] + xv[i].y * wn2[(base + 1) * 4 + node]
           + xv[i].z * wn2[(base + 2) * 4 + node] + xv[i].w * wn2[(base + 3) * 4 + node];
    }
    s = warp_sum(s) + bn2[node];
    int leaf = node * 2 + ((s > 0.f) ? 0 : 1);

    if (lane == 0) {
        int pos = atomicAdd(&g_count[leaf], 1);
        g_list[leaf * TOKENS + pos] = gwarp;
    }
}

// Per (leaf, 32-token tile): H = (X@W1a+b1a)*(X@W1b+b1b); Y = H@W2 + b2; scatter.
__global__ void __launch_bounds__(256) ffn_kernel(
    const float* __restrict__ x,
    const float* __restrict__ w1a, const float* __restrict__ b1a,
    const float* __restrict__ w1b, const float* __restrict__ b1b,
    const float* __restrict__ w2,  const float* __restrict__ b2,
    float* __restrict__ out)
{
    int leaf  = blockIdx.y;
    int cnt   = g_count[leaf];
    int start = blockIdx.x * BM;
    if (start >= cnt) return;
    int rows = min(BM, cnt - start);
    const int* list = g_list + leaf * TOKENS + start;

    __shared__ float Xs[BM][BK];          // 2 KB
    __shared__ float Ws[BK][256];         // 16 KB
    __shared__ float Hs[BM][FDIM];        // 16 KB
    __shared__ int   rowTok[BM];

    int tid = threadIdx.x;
    int tx  = tid & 31;   // 0..31 -> column groups
    int ty  = tid >> 5;   // 0..7  -> row groups (4 rows each)

    if (tid < BM) rowTok[tid] = list[min(tid, rows - 1)];
    __syncthreads();

    const float* W1a = w1a + (size_t)leaf * DIM * FDIM;
    const float* W1b = w1b + (size_t)leaf * DIM * FDIM;

    // ---------- GEMM1: C[32,256] = X[32,512] @ [W1a | W1b] ----------
    // thread cols: j<4 -> f = tx*4+j (W1a side); j>=4 -> same f on W1b side
    float acc[4][8];
    #pragma unroll
    for (int i = 0; i < 4; i++)
        #pragma unroll
        for (int j = 0; j < 8; j++) acc[i][j] = 0.f;

    for (int k0 = 0; k0 < DIM; k0 += BK) {
        if (tid < 128) {                    // Xs: 32 rows x 4 float4
            int r = tid >> 2, c4 = tid & 3;
            float4 v = *(const float4*)(x + (size_t)rowTok[r] * DIM + k0 + c4 * 4);
            *(float4*)&Xs[r][c4 * 4] = v;
        }
        #pragma unroll
        for (int r = 0; r < 4; r++) {       // Ws: 16 x 256 (W1a cols 0..127, W1b cols 128..255)
            int idx  = tid + r * 256;
            int krow = idx >> 6;
            int col  = (idx & 63) * 4;
            const float* src = (col < FDIM) ? (W1a + (size_t)(k0 + krow) * FDIM + col)
                                            : (W1b + (size_t)(k0 + krow) * FDIM + (col - FDIM));
            *(float4*)&Ws[krow][col] = *(const float4*)src;
        }
        __syncthreads();
        #pragma unroll
        for (int kk = 0; kk < BK; kk++) {
            float a[4];
            #pragma unroll
            for (int i = 0; i < 4; i++) a[i] = Xs[ty * 4 + i][kk];
            float4 bA = *(float4*)&Ws[kk][tx * 4];
            float4 bB = *(float4*)&Ws[kk][128 + tx * 4];
            #pragma unroll
            for (int i = 0; i < 4; i++) {
                acc[i][0] += a[i] * bA.x;  acc[i][1] += a[i] * bA.y;
                acc[i][2] += a[i] * bA.z;  acc[i][3] += a[i] * bA.w;
                acc[i][4] += a[i] * bB.x;  acc[i][5] += a[i] * bB.y;
                acc[i][6] += a[i] * bB.z;  acc[i][7] += a[i] * bB.w;
            }
        }
        __syncthreads();
    }

    // Gate in-register -> Hs
    {
        float4 ba = *(const float4*)(b1a + leaf * FDIM + tx * 4);
        float4 bb = *(const float4*)(b1b + leaf * FDIM + tx * 4);
        #pragma unroll
        for (int i = 0; i < 4; i++) {
            float4 h;
            h.x = (acc[i][0] + ba.x) * (acc[i][4] + bb.x);
            h.y = (acc[i][1] + ba.y) * (acc[i][5] + bb.y);
            h.z = (acc[i][2] + ba.z) * (acc[i][6] + bb.z);
            h.w = (acc[i][3] + ba.w) * (acc[i][7] + bb.w);
            *(float4*)&Hs[ty * 4 + i][tx * 4] = h;
        }
    }
    __syncthreads();

    // ---------- GEMM2: Y[32,512] = Hs[32,128] @ W2[128,512], two 256-col passes ----------
    const float* W2 = w2 + (size_t)leaf * FDIM * DIM;
    for (int n0 = 0; n0 < DIM; n0 += 256) {
        float acc2[4][8];
        #pragma unroll
        for (int i = 0; i < 4; i++)
            #pragma unroll
            for (int j = 0; j < 8; j++) acc2[i][j] = 0.f;

        for (int k0 = 0; k0 < FDIM; k0 += BK) {
            __syncthreads();                // protect Ws reuse
            #pragma unroll
            for (int r = 0; r < 4; r++) {
                int idx  = tid + r * 256;
                int krow = idx >> 6;
                int col  = (idx & 63) * 4;
                *(float4*)&Ws[krow][col] =
                    *(const float4*)(W2 + (size_t)(k0 + krow) * DIM + n0 + col);
            }
            __syncthreads();
            #pragma unroll
            for (int kk = 0; kk < BK; kk++) {
                float a[4];
                #pragma unroll
                for (int i = 0; i < 4; i++) a[i] = Hs[ty * 4 + i][k0 + kk];
                float4 b0 = *(float4*)&Ws[kk][tx * 8];
                float4 b1 = *(float4*)&Ws[kk][tx * 8 + 4];
                #pragma unroll
                for (int i = 0; i < 4; i++) {
                    acc2[i][0] += a[i] * b0.x;  acc2[i][1] += a[i] * b0.y;
                    acc2[i][2] += a[i] * b0.z;  acc2[i][3] += a[i] * b0.w;
                    acc2[i][4] += a[i] * b1.x;  acc2[i][5] += a[i] * b1.y;
                    acc2[i][6] += a[i] * b1.z;  acc2[i][7] += a[i] * b1.w;
                }
            }
        }

        float4 c0 = *(const float4*)(b2 + leaf * DIM + n0 + tx * 8);
        float4 c1 = *(const float4*)(b2 + leaf * DIM + n0 + tx * 8 + 4);
        #pragma unroll
        for (int i = 0; i < 4; i++) {
            int r = ty * 4 + i;
            if (r < rows) {
                float* orow = out + (size_t)rowTok[r] * DIM + n0 + tx * 8;
                float4 v0, v1;
                v0.x = acc2[i][0] + c0.x;  v0.y = acc2[i][1] + c0.y;
                v0.z = acc2[i][2] + c0.z;  v0.w = acc2[i][3] + c0.w;
                v1.x = acc2[i][4] + c1.x;  v1.y = acc2[i][5] + c1.y;
                v1.z = acc2[i][6] + c1.z;  v1.w = acc2[i][7] + c1.w;
                *(float4*)orow       = v0;
                *(float4*)(orow + 4) = v1;
            }
        }
    }
}

extern "C" void kernel_launch(void* const* d_in, const int* in_sizes, int n_in,
                              void* d_out, int out_size)
{
    const float* x   = (const float*)d_in[0];
    // d_in[1] = training (forward value identical either way; ignored)
    const float* wn0 = (const float*)d_in[2];
    const float* bn0 = (const float*)d_in[3];
    const float* wn1 = (const float*)d_in[4];
    const float* bn1 = (const float*)d_in[5];
    const float* wn2 = (const float*)d_in[6];
    const float* bn2 = (const float*)d_in[7];
    const float* w1a = (const float*)d_in[8];
    const float* b1a = (const float*)d_in[9];
    const float* w1b = (const float*)d_in[10];
    const float* b1b = (const float*)d_in[11];
    const float* w2  = (const float*)d_in[12];
    const float* b2  = (const float*)d_in[13];
    float* out = (float*)d_out;

    zero_kernel<<<1, 32>>>();
    route_kernel<<<(TOKENS * 32) / 256, 256>>>(x, wn0, bn0, wn1, bn1, wn2, bn2);
    dim3 grid(TILES_PER_LEAF, NLEAF);
    ffn_kernel<<<grid, 256>>>(x, w1a, b1a, w1b, b1b, w2, b2, out);
}

// round 2
// speedup vs baseline: 1.0789x; 1.0789x over previous
#include <cuda_runtime.h>

#define TOKENS 8192
#define DIM    512
#define FDIM   128
#define NLEAF  8
#define BM     32
#define BK     32
#define TILES_PER_LEAF (TOKENS / BM)   // 256

typedef unsigned long long ull;

// Scratch (static device globals — no allocation in kernel_launch)
__device__ int g_count[NLEAF];
__device__ int g_list[NLEAF * TOKENS];

__global__ void zero_kernel() {
    if (threadIdx.x < NLEAF) g_count[threadIdx.x] = 0;
}

__device__ __forceinline__ float warp_sum(float v) {
    #pragma unroll
    for (int o = 16; o > 0; o >>= 1) v += __shfl_xor_sync(0xFFFFFFFFu, v, o);
    return v;
}

// --- packed f32x2 helpers (Blackwell: drives both halves of the fp32 pipe) ---
__device__ __forceinline__ ull pack2(float x, float y) {
    ull r;
    asm("mov.b64 %0, {%1, %2};" : "=l"(r) : "f"(x), "f"(y));
    return r;
}
__device__ __forceinline__ void unpack2(ull v, float &x, float &y) {
    asm("mov.b64 {%0, %1}, %2;" : "=f"(x), "=f"(y) : "l"(v));
}
__device__ __forceinline__ void ffma2(ull &acc, ull a, ull b) {
    asm("fma.rn.f32x2 %0, %1, %2, %0;" : "+l"(acc) : "l"(a), "l"(b));
}

// One warp per token: 3 path-dependent routing dots, then bucket the token.
__global__ void route_kernel(const float* __restrict__ x,
                             const float* __restrict__ wn0, const float* __restrict__ bn0,
                             const float* __restrict__ wn1, const float* __restrict__ bn1,
                             const float* __restrict__ wn2, const float* __restrict__ bn2)
{
    int gwarp = (blockIdx.x * blockDim.x + threadIdx.x) >> 5;
    int lane  = threadIdx.x & 31;
    if (gwarp >= TOKENS) return;

    const float4* xr4 = (const float4*)(x + (size_t)gwarp * DIM);
    float4 xv[4];
    #pragma unroll
    for (int i = 0; i < 4; i++) xv[i] = xr4[lane + i * 32];

    float s = 0.f;
    #pragma unroll
    for (int i = 0; i < 4; i++) {
        int base = (lane + i * 32) * 4;
        s += xv[i].x * wn0[base + 0] + xv[i].y * wn0[base + 1]
           + xv[i].z * wn0[base + 2] + xv[i].w * wn0[base + 3];
    }
    s = warp_sum(s) + bn0[0];
    int node = (s > 0.f) ? 0 : 1;

    s = 0.f;
    #pragma unroll
    for (int i = 0; i < 4; i++) {
        int base = (lane + i * 32) * 4;
        s += xv[i].x * wn1[(base + 0) * 2 + node] + xv[i].y * wn1[(base + 1) * 2 + node]
           + xv[i].z * wn1[(base + 2) * 2 + node] + xv[i].w * wn1[(base + 3) * 2 + node];
    }
    s = warp_sum(s) + bn1[node];
    node = node * 2 + ((s > 0.f) ? 0 : 1);

    s = 0.f;
    #pragma unroll
    for (int i = 0; i < 4; i++) {
        int base = (lane + i * 32) * 4;
        s += xv[i].x * wn2[(base + 0) * 4 + node] + xv[i].y * wn2[(base + 1) * 4 + node]
           + xv[i].z * wn2[(base + 2) * 4 + node] + xv[i].w * wn2[(base + 3) * 4 + node];
    }
    s = warp_sum(s) + bn2[node];
    int leaf = node * 2 + ((s > 0.f) ? 0 : 1);

    if (lane == 0) {
        int pos = atomicAdd(&g_count[leaf], 1);
        g_list[leaf * TOKENS + pos] = gwarp;
    }
}

// Per (leaf, 32-token tile): H = (X@W1a+b1a)*(X@W1b+b1b); Y = H@W2 + b2; scatter.
// blockIdx.x = leaf (fastest-varying -> all work tiles land in the first wave),
// blockIdx.y = tile.
__global__ void __launch_bounds__(256) ffn_kernel(
    const float* __restrict__ x,
    const float* __restrict__ w1a, const float* __restrict__ b1a,
    const float* __restrict__ w1b, const float* __restrict__ b1b,
    const float* __restrict__ w2,  const float* __restrict__ b2,
    float* __restrict__ out)
{
    int leaf  = blockIdx.x;
    int cnt   = g_count[leaf];
    int start = blockIdx.y * BM;
    if (start >= cnt) return;
    int rows = min(BM, cnt - start);
    const int* list = g_list + leaf * TOKENS + start;

    __shared__ float Xs[BM][BK];          // 4 KB
    __shared__ float Ws[BK][256];         // 32 KB
    __shared__ float Hs[BM][FDIM];        // 16 KB
    __shared__ int   rowTok[BM];

    int tid = threadIdx.x;
    int tx  = tid & 31;   // column group
    int ty  = tid >> 5;   // row group (4 rows each)

    if (tid < BM) rowTok[tid] = list[min(tid, rows - 1)];
    __syncthreads();

    const float* W1a = w1a + (size_t)leaf * DIM * FDIM;
    const float* W1b = w1b + (size_t)leaf * DIM * FDIM;

    // ---------- GEMM1: C[32,256] = X[32,512] @ [W1a | W1b] ----------
    // acc pairs over adjacent columns: accp[i][0..1] = W1a cols tx*4..+3,
    //                                  accp[i][2..3] = W1b cols tx*4..+3
    ull accp[4][4];
    #pragma unroll
    for (int i = 0; i < 4; i++)
        #pragma unroll
        for (int j = 0; j < 4; j++) accp[i][j] = 0ull;

    for (int k0 = 0; k0 < DIM; k0 += BK) {
        {   // Xs: 32 rows x 32 floats, one float4 per thread, linear layout
            int r = tid >> 3, c4 = tid & 7;
            *(float4*)&Xs[r][c4 * 4] =
                *(const float4*)(x + (size_t)rowTok[r] * DIM + k0 + c4 * 4);
        }
        #pragma unroll
        for (int r = 0; r < 8; r++) {       // Ws: 32 x 256 (W1a | W1b)
            int idx  = tid + r * 256;
            int krow = idx >> 6;
            int col  = (idx & 63) * 4;
            const float* src = (col < FDIM) ? (W1a + (size_t)(k0 + krow) * FDIM + col)
                                            : (W1b + (size_t)(k0 + krow) * FDIM + (col - FDIM));
            *(float4*)&Ws[krow][col] = *(const float4*)src;
        }
        __syncthreads();
        #pragma unroll
        for (int kk = 0; kk < BK; kk++) {
            ull aa[4];
            #pragma unroll
            for (int i = 0; i < 4; i++) {
                float av = Xs[ty * 4 + i][kk];      // broadcast LDS
                aa[i] = pack2(av, av);
            }
            ulonglong2 bA = *(ulonglong2*)&Ws[kk][tx * 4];         // LDS.128 = 2 packed pairs
            ulonglong2 bB = *(ulonglong2*)&Ws[kk][128 + tx * 4];
            #pragma unroll
            for (int i = 0; i < 4; i++) {
                ffma2(accp[i][0], aa[i], bA.x);
                ffma2(accp[i][1], aa[i], bA.y);
                ffma2(accp[i][2], aa[i], bB.x);
                ffma2(accp[i][3], aa[i], bB.y);
            }
        }
        __syncthreads();
    }

    // Gate -> Hs
    {
        float4 ba = *(const float4*)(b1a + leaf * FDIM + tx * 4);
        float4 bb = *(const float4*)(b1b + leaf * FDIM + tx * 4);
        #pragma unroll
        for (int i = 0; i < 4; i++) {
            float a0,a1,a2,a3, g0,g1,g2,g3;
            unpack2(accp[i][0], a0, a1);
            unpack2(accp[i][1], a2, a3);
            unpack2(accp[i][2], g0, g1);
            unpack2(accp[i][3], g2, g3);
            float4 h;
            h.x = (a0 + ba.x) * (g0 + bb.x);
            h.y = (a1 + ba.y) * (g1 + bb.y);
            h.z = (a2 + ba.z) * (g2 + bb.z);
            h.w = (a3 + ba.w) * (g3 + bb.w);
            *(float4*)&Hs[ty * 4 + i][tx * 4] = h;
        }
    }

    // ---------- GEMM2: Y[32,512] = Hs[32,128] @ W2[128,512], two 256-col passes ----------
    const float* W2 = w2 + (size_t)leaf * FDIM * DIM;
    for (int n0 = 0; n0 < DIM; n0 += 256) {
        ull acc2p[4][4];
        #pragma unroll
        for (int i = 0; i < 4; i++)
            #pragma unroll
            for (int j = 0; j < 4; j++) acc2p[i][j] = 0ull;

        for (int k0 = 0; k0 < FDIM; k0 += BK) {
            __syncthreads();                // Hs written / Ws reuse
            #pragma unroll
            for (int r = 0; r < 8; r++) {
                int idx  = tid + r * 256;
                int krow = idx >> 6;
                int col  = (idx & 63) * 4;
                *(float4*)&Ws[krow][col] =
                    *(const float4*)(W2 + (size_t)(k0 + krow) * DIM + n0 + col);
            }
            __syncthreads();
            #pragma unroll
            for (int kk = 0; kk < BK; kk++) {
                ull aa[4];
                #pragma unroll
                for (int i = 0; i < 4; i++) {
                    float av = Hs[ty * 4 + i][k0 + kk];   // broadcast LDS
                    aa[i] = pack2(av, av);
                }
                ulonglong2 b0 = *(ulonglong2*)&Ws[kk][tx * 8];
                ulonglong2 b1 = *(ulonglong2*)&Ws[kk][tx * 8 + 4];
                #pragma unroll
                for (int i = 0; i < 4; i++) {
                    ffma2(acc2p[i][0], aa[i], b0.x);
                    ffma2(acc2p[i][1], aa[i], b0.y);
                    ffma2(acc2p[i][2], aa[i], b1.x);
                    ffma2(acc2p[i][3], aa[i], b1.y);
                }
            }
        }

        float4 c0 = *(const float4*)(b2 + leaf * DIM + n0 + tx * 8);
        float4 c1 = *(const float4*)(b2 + leaf * DIM + n0 + tx * 8 + 4);
        #pragma unroll
        for (int i = 0; i < 4; i++) {
            int r = ty * 4 + i;
            if (r < rows) {
                float y0,y1,y2,y3,y4,y5,y6,y7;
                unpack2(acc2p[i][0], y0, y1);
                unpack2(acc2p[i][1], y2, y3);
                unpack2(acc2p[i][2], y4, y5);
                unpack2(acc2p[i][3], y6, y7);
                float* orow = out + (size_t)rowTok[r] * DIM + n0 + tx * 8;
                float4 v0, v1;
                v0.x = y0 + c0.x;  v0.y = y1 + c0.y;
                v0.z = y2 + c0.z;  v0.w = y3 + c0.w;
                v1.x = y4 + c1.x;  v1.y = y5 + c1.y;
                v1.z = y6 + c1.z;  v1.w = y7 + c1.w;
                *(float4*)orow       = v0;
                *(float4*)(orow + 4) = v1;
            }
        }
    }
}

extern "C" void kernel_launch(void* const* d_in, const int* in_sizes, int n_in,
                              void* d_out, int out_size)
{
    const float* x   = (const float*)d_in[0];
    // d_in[1] = training (forward value identical either way; ignored)
    const float* wn0 = (const float*)d_in[2];
    const float* bn0 = (const float*)d_in[3];
    const float* wn1 = (const float*)d_in[4];
    const float* bn1 = (const float*)d_in[5];
    const float* wn2 = (const float*)d_in[6];
    const float* bn2 = (const float*)d_in[7];
    const float* w1a = (const float*)d_in[8];
    const float* b1a = (const float*)d_in[9];
    const float* w1b = (const float*)d_in[10];
    const float* b1b = (const float*)d_in[11];
    const float* w2  = (const float*)d_in[12];
    const float* b2  = (const float*)d_in[13];
    float* out = (float*)d_out;

    zero_kernel<<<1, 32>>>();
    route_kernel<<<(TOKENS * 32) / 256, 256>>>(x, wn0, bn0, wn1, bn1, wn2, bn2);
    dim3 grid(NLEAF, TILES_PER_LEAF);   // leaf fastest: all work tiles in wave 1
    ffn_kernel<<<grid, 256>>>(x, w1a, b1a, w1b, b1b, w2, b2, out);
}